// round 2
// baseline (speedup 1.0000x reference)
#include <cuda_runtime.h>
#include <cstdint>
#include <cstddef>

#define B_  256
#define T_  512
#define E_  200
#define H_  100
#define G3_ 300
#define NC_ 5

// 256*512*300 floats = 157 MB scratch for GRU input preactivations.
__device__ float g_xp[39321600];

__device__ __forceinline__ float sigmoidf_(float x) {
    return 1.0f / (1.0f + __expf(-x));
}

// ---------------------------------------------------------------------------
// Kernel A: xp[row,:] = scale(row) * (emb[txt[row]] @ W_ih^T) + b_ih
// row = b*T + t. 32 rows x 300 cols per block; per-thread 4x10 register tile.
// ---------------------------------------------------------------------------
__global__ void __launch_bounds__(256) xp_kernel(
    const int* __restrict__ txt, const float* __restrict__ emb,
    const float* __restrict__ W_ih, const float* __restrict__ b_ih)
{
    __shared__ float es[32][200];
    __shared__ float ws[300][11];   // k-chunk of 10 (+1 pad)
    __shared__ float sc[32];
    __shared__ float n2[32];
    __shared__ int   toks[32];

    const int tid  = threadIdx.x;
    const int row0 = blockIdx.x * 32;

    if (tid < 32) { toks[tid] = txt[row0 + tid]; n2[tid] = 0.f; }
    __syncthreads();

    // gather raw embedding rows
    for (int idx = tid; idx < 32 * 200; idx += 256) {
        int r = idx / 200, k = idx - r * 200;
        es[r][k] = emb[(size_t)toks[r] * E_ + k];
    }
    __syncthreads();

    // row norms
    if (tid < 128) {
        int r = tid & 31, q = tid >> 5;
        float p = 0.f;
        for (int k = q * 50; k < q * 50 + 50; ++k) { float v = es[r][k]; p = fmaf(v, v, p); }
        atomicAdd(&n2[r], p);
    }
    __syncthreads();
    if (tid < 32) {
        float n = sqrtf(n2[tid]);
        sc[tid] = (n > 1.0f) ? 1.0f / (n + 1e-7f) : 1.0f;
    }
    __syncthreads();

    const int cg = tid % 30;   // cols cg*10 .. cg*10+9
    const int rg = tid / 30;   // rows rg*4 .. rg*4+3 (active if tid<240)

    float acc[4][10];
    #pragma unroll
    for (int i = 0; i < 4; i++)
        #pragma unroll
        for (int j = 0; j < 10; j++) acc[i][j] = 0.f;

    for (int k0 = 0; k0 < 200; k0 += 10) {
        for (int idx = tid; idx < 3000; idx += 256) {
            int c = idx / 10, k = idx - c * 10;
            ws[c][k] = W_ih[c * 200 + k0 + k];
        }
        __syncthreads();
        if (tid < 240) {
            #pragma unroll
            for (int k = 0; k < 10; k++) {
                float e0 = es[rg * 4 + 0][k0 + k];
                float e1 = es[rg * 4 + 1][k0 + k];
                float e2 = es[rg * 4 + 2][k0 + k];
                float e3 = es[rg * 4 + 3][k0 + k];
                #pragma unroll
                for (int j = 0; j < 10; j++) {
                    float wv = ws[cg * 10 + j][k];
                    acc[0][j] = fmaf(e0, wv, acc[0][j]);
                    acc[1][j] = fmaf(e1, wv, acc[1][j]);
                    acc[2][j] = fmaf(e2, wv, acc[2][j]);
                    acc[3][j] = fmaf(e3, wv, acc[3][j]);
                }
            }
        }
        __syncthreads();
    }

    if (tid < 240) {
        float bih[10];
        #pragma unroll
        for (int j = 0; j < 10; j++) bih[j] = b_ih[cg * 10 + j];
        #pragma unroll
        for (int i = 0; i < 4; i++) {
            int r = rg * 4 + i;
            float s = sc[r];
            size_t base = (size_t)(row0 + r) * G3_ + cg * 10;
            #pragma unroll
            for (int j = 0; j < 10; j++)
                g_xp[base + j] = fmaf(s, acc[i][j], bih[j]);
        }
    }
}

// ---------------------------------------------------------------------------
// Kernel B: fused GRU scan + attention gate + second recurrence + output head.
// One CTA per batch element. Weights resident in shared memory.
// ---------------------------------------------------------------------------

// dot product of two 100-float vectors in shared memory (both 16B aligned)
__device__ __forceinline__ float dot100(const float* __restrict__ w,
                                        const float* __restrict__ v)
{
    float acc = 0.f;
    #pragma unroll
    for (int k = 0; k < 100; k += 4) {
        float4 a = *reinterpret_cast<const float4*>(w + k);
        float4 b = *reinterpret_cast<const float4*>(v + k);
        acc = fmaf(a.x, b.x, acc);
        acc = fmaf(a.y, b.y, acc);
        acc = fmaf(a.z, b.z, acc);
        acc = fmaf(a.w, b.w, acc);
    }
    return acc;
}

// dynamic smem layout (float indices)
#define OFF_WHH  0        // 30000
#define OFF_WTI  30000    // 10000
#define OFF_WTS  40000    // 10000
#define OFF_BHH  50000    // 300
#define OFF_BTS  50300    // 100
#define OFF_BTI  50400    // 100
#define OFF_WLQ  50500    // 100  W_lgr[0, 0:100]
#define OFF_WLS  50600    // 100  W_lgr[0, 100:200]
#define OFF_H    50700    // 100
#define OFF_S    50800    // 100
#define OFF_HP   50900    // 300
#define OFF_TIV  51200    // 100
#define OFF_TSS  51300    // 100
#define OFF_XS   51400    // 300
#define OFF_SCAL 51700    // 8
#define SMEM_B_FLOATS 51708
#define SMEM_B_BYTES  (SMEM_B_FLOATS * 4)

__global__ void __launch_bounds__(512, 1) scan_kernel(
    const int*   __restrict__ lens,
    const float* __restrict__ W_hh, const float* __restrict__ b_hh,
    const float* __restrict__ W_lgr, const float* __restrict__ b_lgr,
    const float* __restrict__ W_ts, const float* __restrict__ b_ts,
    const float* __restrict__ W_ti, const float* __restrict__ b_ti,
    const float* __restrict__ W_out, const float* __restrict__ b_out,
    float* __restrict__ out)
{
    extern __shared__ float sm[];
    float* WHH = sm + OFF_WHH;
    float* WTI = sm + OFF_WTI;
    float* WTS = sm + OFF_WTS;
    float* BHH = sm + OFF_BHH;
    float* BTS = sm + OFF_BTS;
    float* BTI = sm + OFF_BTI;
    float* WLQ = sm + OFF_WLQ;
    float* WLS = sm + OFF_WLS;
    float* hs  = sm + OFF_H;
    float* ss  = sm + OFF_S;
    float* hp  = sm + OFF_HP;
    float* tiv = sm + OFF_TIV;
    float* tss = sm + OFF_TSS;
    float* xs  = sm + OFF_XS;
    float* scal= sm + OFF_SCAL;

    const int tid = threadIdx.x;
    const int b   = blockIdx.x;

    // stage weights
    for (int i = tid; i < 30000; i += 512) WHH[i] = W_hh[i];
    for (int i = tid; i < 10000; i += 512) WTI[i] = W_ti[i];
    for (int i = tid; i < 10000; i += 512) WTS[i] = W_ts[i];
    if (tid < 300) BHH[tid] = b_hh[tid];
    if (tid < 100) {
        BTS[tid] = b_ts[tid];
        BTI[tid] = b_ti[tid];
        WLQ[tid] = W_lgr[tid];
        WLS[tid] = W_lgr[100 + tid];
        hs[tid]  = 0.f;
        ss[tid]  = 0.f;
    }
    const float blgr = b_lgr[0];
    const int   len  = lens[b];

    const float* xpb = g_xp + (size_t)b * T_ * G3_;
    float xv = (tid < 300) ? xpb[tid] : 0.f;   // prefetch t=0
    __syncthreads();

    const int wid  = tid >> 5;
    const int lane = tid & 31;

    for (int t = 0; t < T_; ++t) {
        // ---- P1: uses h_{t-1}, state_{t-1} ----
        if (tid < 300) {
            xs[tid] = xv;
            hp[tid] = BHH[tid] + dot100(WHH + tid * 100, hs);
        } else if (tid >= 400 && tid < 500) {
            tss[tid - 400] = dot100(WTS + (tid - 400) * 100, ss);
        }
        if (tid < 300 && t + 1 < T_) xv = xpb[(size_t)(t + 1) * G3_ + tid];
        __syncthreads();

        // ---- P2: GRU elementwise, produce h_t ----
        if (tid < 100) {
            float r  = sigmoidf_(xs[tid]       + hp[tid]);
            float z  = sigmoidf_(xs[100 + tid] + hp[100 + tid]);
            float ng = tanhf    (xs[200 + tid] + r * hp[200 + tid]);
            hs[tid] = (1.f - z) * ng + z * hs[tid];
        }
        __syncthreads();

        // ---- P3: ti from h_t; scalar reductions ----
        if (tid >= 300 && tid < 400) {
            tiv[tid - 300] = dot100(WTI + (tid - 300) * 100, hs);
        } else if (wid < 4) {
            float v;
            if (wid == 0) {          // sum(h)
                v = hs[lane] + hs[lane + 32] + hs[lane + 64]
                  + ((lane < 4) ? hs[lane + 96] : 0.f);
            } else if (wid == 1) {   // sum(h^2)
                float a = hs[lane], c = hs[lane + 32], d = hs[lane + 64];
                float e = (lane < 4) ? hs[lane + 96] : 0.f;
                v = a * a + c * c + d * d + e * e;
            } else if (wid == 2) {   // lgr_in = W_lgr[:,:100] . h
                v = WLQ[lane] * hs[lane] + WLQ[lane + 32] * hs[lane + 32]
                  + WLQ[lane + 64] * hs[lane + 64]
                  + ((lane < 4) ? WLQ[lane + 96] * hs[lane + 96] : 0.f);
            } else {                 // Wls . state_{t-1}
                v = WLS[lane] * ss[lane] + WLS[lane + 32] * ss[lane + 32]
                  + WLS[lane + 64] * ss[lane + 64]
                  + ((lane < 4) ? WLS[lane + 96] * ss[lane + 96] : 0.f);
            }
            #pragma unroll
            for (int o = 16; o > 0; o >>= 1) v += __shfl_xor_sync(0xffffffffu, v, o);
            if (lane == 0) scal[wid] = v;
        }
        __syncthreads();

        // ---- P4: second recurrence state update ----
        if (tid < 100) {
            float hsum = scal[0], h2 = scal[1], li = scal[2], wd = scal[3];
            float att  = 0.001f * hsum / fmaxf(sqrtf(h2), 1e-12f);
            float zt   = (t < len) ? fmaxf(att, 0.f) : 0.f;
            float gate = sigmoidf_(li + wd + blgr);
            float ns   = tanhf(tiv[tid] + BTI[tid] + gate * tss[tid] + BTS[tid]);
            ss[tid] = (1.f - zt) * ss[tid] + zt * ns;
        }
        __syncthreads();
    }

    // output head: out[b, c] = W_out[c] . state + b_out[c]
    if (tid < NC_) {
        float a = b_out[tid];
        for (int k = 0; k < 100; ++k)
            a = fmaf(W_out[tid * 100 + k], ss[k], a);
        out[b * NC_ + tid] = a;
    }
}

extern "C" void kernel_launch(void* const* d_in, const int* in_sizes, int n_in,
                              void* d_out, int out_size)
{
    const int*   txt   = (const int*)  d_in[0];
    const int*   lens  = (const int*)  d_in[1];
    const float* emb   = (const float*)d_in[2];
    const float* W_ih  = (const float*)d_in[3];
    const float* W_hh  = (const float*)d_in[4];
    const float* b_ih  = (const float*)d_in[5];
    const float* b_hh  = (const float*)d_in[6];
    const float* W_lgr = (const float*)d_in[7];
    const float* b_lgr = (const float*)d_in[8];
    const float* W_ts  = (const float*)d_in[9];
    const float* b_ts  = (const float*)d_in[10];
    const float* W_ti  = (const float*)d_in[11];
    const float* b_ti  = (const float*)d_in[12];
    const float* W_out = (const float*)d_in[13];
    const float* b_out = (const float*)d_in[14];
    float* out = (float*)d_out;

    // Opt-in to >48KB dynamic smem. Takes effect on the first (uncaptured)
    // correctness call; harmless no-op afterwards. Return value ignored.
    cudaFuncSetAttribute(scan_kernel,
                         cudaFuncAttributeMaxDynamicSharedMemorySize,
                         SMEM_B_BYTES);

    xp_kernel<<<(B_ * T_) / 32, 256>>>(txt, emb, W_ih, b_ih);
    scan_kernel<<<B_, 512, SMEM_B_BYTES>>>(lens,
                                           W_hh, b_hh, W_lgr, b_lgr,
                                           W_ts, b_ts, W_ti, b_ti,
                                           W_out, b_out, out);
}

// round 3
// speedup vs baseline: 1.1278x; 1.1278x over previous
#include <cuda_runtime.h>
#include <cstdint>
#include <cstddef>

#define B_  256
#define T_  512
#define E_  200
#define H_  100
#define G3_ 300
#define NC_ 5

typedef unsigned long long ull;

// 256*512*300 floats = 157 MB scratch for GRU input preactivations.
__device__ float g_xp[39321600];

// packed fp32x2 FMA / ADD (Blackwell sm_103a); exact per-lane fp32 semantics
#define FMA2(d, a, b, c) \
    asm("fma.rn.f32x2 %0, %1, %2, %3;" : "=l"(d) : "l"(a), "l"(b), "l"(c))
#define ADD2(d, a, b) \
    asm("add.rn.f32x2 %0, %1, %2;" : "=l"(d) : "l"(a), "l"(b))

__device__ __forceinline__ float sigmoidf_(float x) {
    return 1.0f / (1.0f + __expf(-x));
}

__device__ __forceinline__ float lo_of(ull v) {
    float a, b_;
    asm("mov.b64 {%0, %1}, %2;" : "=f"(a), "=f"(b_) : "l"(v));
    return a;
}
__device__ __forceinline__ float sum2(ull v) {
    float a, b_;
    asm("mov.b64 {%0, %1}, %2;" : "=f"(a), "=f"(b_) : "l"(v));
    return a + b_;
}

// ---------------------------------------------------------------------------
// Kernel A: xp[row,:] = scale(row) * (emb[txt[row]] @ W_ih^T) + b_ih
// 32 rows x 300 cols per block; per-thread 4x10 tile computed as 4x5 f32x2.
// Embedding values duplicated into both f32x2 lanes in SMEM; weights staged
// [k][c] so column pairs load as 64-bit.
// ---------------------------------------------------------------------------
#define A_ESD_OFF   0                       // float2[32][200] = 51200 B
#define A_WST_OFF   51200                   // float[10][300]  = 12000 B
#define A_SC_OFF    (51200 + 12000)         // float[32]
#define A_N2_OFF    (A_SC_OFF + 128)        // float[32]
#define A_TOK_OFF   (A_N2_OFF + 128)        // int[32]
#define A_SMEM_BYTES (A_TOK_OFF + 128)

__global__ void __launch_bounds__(256) xp_kernel(
    const int* __restrict__ txt, const float* __restrict__ emb,
    const float* __restrict__ W_ih, const float* __restrict__ b_ih)
{
    extern __shared__ char asm_[];
    float2* esd = (float2*)(asm_ + A_ESD_OFF);      // [32][200], dup lanes
    float*  wst = (float*) (asm_ + A_WST_OFF);      // [10][300]
    float*  sc  = (float*) (asm_ + A_SC_OFF);
    float*  n2  = (float*) (asm_ + A_N2_OFF);
    int*    toks= (int*)   (asm_ + A_TOK_OFF);

    const int tid  = threadIdx.x;
    const int row0 = blockIdx.x * 32;

    if (tid < 32) { toks[tid] = txt[row0 + tid]; n2[tid] = 0.f; }
    __syncthreads();

    // gather embedding rows, duplicating each value into both f32x2 lanes
    for (int idx = tid; idx < 32 * 200; idx += 256) {
        int r = idx / 200, k = idx - r * 200;
        float v = emb[(size_t)toks[r] * E_ + k];
        esd[r * 200 + k] = make_float2(v, v);
    }
    __syncthreads();

    // row norms (read .x lane)
    if (tid < 128) {
        int r = tid & 31, q = tid >> 5;
        float p = 0.f;
        for (int k = q * 50; k < q * 50 + 50; ++k) {
            float v = esd[r * 200 + k].x;
            p = fmaf(v, v, p);
        }
        atomicAdd(&n2[r], p);
    }
    __syncthreads();
    if (tid < 32) {
        float n = sqrtf(n2[tid]);
        sc[tid] = (n > 1.0f) ? 1.0f / (n + 1e-7f) : 1.0f;
    }
    __syncthreads();

    const int cg = tid % 30;   // cols cg*10 .. cg*10+9
    const int rg = tid / 30;   // rows rg*4 .. rg*4+3 (active if tid<240)

    ull acc[4][5];
    #pragma unroll
    for (int i = 0; i < 4; i++)
        #pragma unroll
        for (int j = 0; j < 5; j++) acc[i][j] = 0ull;

    for (int k0 = 0; k0 < 200; k0 += 10) {
        // stage W chunk transposed: wst[kk][c] = W_ih[c][k0+kk]
        for (int idx = tid; idx < 3000; idx += 256) {
            int c = idx / 10, kk = idx - c * 10;
            wst[kk * 300 + c] = W_ih[c * 200 + k0 + kk];
        }
        __syncthreads();
        if (tid < 240) {
            #pragma unroll
            for (int kk = 0; kk < 10; kk++) {
                ull e0 = *(const ull*)&esd[(rg * 4 + 0) * 200 + k0 + kk];
                ull e1 = *(const ull*)&esd[(rg * 4 + 1) * 200 + k0 + kk];
                ull e2 = *(const ull*)&esd[(rg * 4 + 2) * 200 + k0 + kk];
                ull e3 = *(const ull*)&esd[(rg * 4 + 3) * 200 + k0 + kk];
                const ull* wr = (const ull*)&wst[kk * 300 + cg * 10];
                #pragma unroll
                for (int j = 0; j < 5; j++) {
                    ull w = wr[j];
                    FMA2(acc[0][j], e0, w, acc[0][j]);
                    FMA2(acc[1][j], e1, w, acc[1][j]);
                    FMA2(acc[2][j], e2, w, acc[2][j]);
                    FMA2(acc[3][j], e3, w, acc[3][j]);
                }
            }
        }
        __syncthreads();
    }

    if (tid < 240) {
        float2 bih[5];
        const float2* bih2 = (const float2*)b_ih;   // 8B-aligned, cg*10 even
        #pragma unroll
        for (int j = 0; j < 5; j++) bih[j] = bih2[cg * 5 + j];
        #pragma unroll
        for (int i = 0; i < 4; i++) {
            int r = rg * 4 + i;
            float s = sc[r];
            float2* outp = (float2*)(g_xp + (size_t)(row0 + r) * G3_ + cg * 10);
            #pragma unroll
            for (int j = 0; j < 5; j++) {
                float2 a = *(float2*)&acc[i][j];
                float2 v;
                v.x = fmaf(s, a.x, bih[j].x);
                v.y = fmaf(s, a.y, bih[j].y);
                outp[j] = v;
            }
        }
    }
}

// ---------------------------------------------------------------------------
// Kernel B: fused GRU scan + attention gate + second recurrence + head.
// One CTA per batch element. Recurrent weights live in REGISTERS:
//   tid   0-299 : W_hh row tid   (100 regs as 50 f32x2)
//   tid 300-399 : W_ti row tid-300 (also stages/prefetches xp)
//   tid 400-499 : W_ts row tid-400
// Dots: fma.rn.f32x2 against broadcast 64-bit SMEM reads of h/s.
// ---------------------------------------------------------------------------
__device__ __forceinline__ float dotreg(const ull* __restrict__ w,
                                        const float* __restrict__ v)
{
    const ull* h2 = (const ull*)v;
    ull a0 = 0ull, a1 = 0ull, a2 = 0ull, a3 = 0ull;
    #pragma unroll
    for (int i = 0; i < 48; i += 4) {
        FMA2(a0, w[i + 0], h2[i + 0], a0);
        FMA2(a1, w[i + 1], h2[i + 1], a1);
        FMA2(a2, w[i + 2], h2[i + 2], a2);
        FMA2(a3, w[i + 3], h2[i + 3], a3);
    }
    FMA2(a0, w[48], h2[48], a0);
    FMA2(a1, w[49], h2[49], a1);
    ull t0, t1;
    ADD2(t0, a0, a1);
    ADD2(t1, a2, a3);
    ADD2(t0, t0, t1);
    return sum2(t0);
}

__global__ void __launch_bounds__(512, 1) scan_kernel(
    const int*   __restrict__ lens,
    const float* __restrict__ W_hh, const float* __restrict__ b_hh,
    const float* __restrict__ W_lgr, const float* __restrict__ b_lgr,
    const float* __restrict__ W_ts, const float* __restrict__ b_ts,
    const float* __restrict__ W_ti, const float* __restrict__ b_ti,
    const float* __restrict__ W_out, const float* __restrict__ b_out,
    float* __restrict__ out)
{
    __shared__ __align__(16) float hs[100];
    __shared__ __align__(16) float ss[100];
    __shared__ __align__(16) float hp[300];
    __shared__ __align__(16) float xs[300];
    __shared__ __align__(16) float tiv[100];
    __shared__ __align__(16) float tss[100];
    __shared__ __align__(16) float WLQ[100];
    __shared__ __align__(16) float WLS[100];
    __shared__ float scal[4];

    const int tid = threadIdx.x;
    const int b   = blockIdx.x;

    // per-thread weight row -> registers (50 x f32x2)
    const float* wp = W_hh;
    float brow = 0.f;
    if (tid < 300)      { wp = W_hh + tid * 100; brow = b_hh[tid]; }
    else if (tid < 400) { wp = W_ti + (tid - 300) * 100; }
    else if (tid < 500) { wp = W_ts + (tid - 400) * 100; }
    ull w[50];
    {
        const ull* p = (const ull*)wp;   // rows are 400B apart -> 8B aligned
        #pragma unroll
        for (int i = 0; i < 50; i++) w[i] = p[i];
    }

    if (tid < 100) {
        WLQ[tid] = W_lgr[tid];
        WLS[tid] = W_lgr[100 + tid];
        hs[tid]  = 0.f;
        ss[tid]  = 0.f;
    }
    float bts = 0.f, bti = 0.f;
    if (tid < 100) { bts = b_ts[tid]; bti = b_ti[tid]; }
    const float blgr = b_lgr[0];
    const int   len  = lens[b];

    const float* xpb = g_xp + (size_t)b * T_ * G3_;
    float xv0 = 0.f, xv1 = 0.f, xv2 = 0.f;      // prefetch t=0
    if (tid >= 300 && tid < 400) {
        int j = tid - 300;
        xv0 = xpb[j]; xv1 = xpb[j + 100]; xv2 = xpb[j + 200];
    }
    __syncthreads();

    const int wid  = tid >> 5;
    const int lane = tid & 31;

    for (int t = 0; t < T_; ++t) {
        // ---- P1: dots on h_{t-1}, s_{t-1}; xp staging + prefetch ----
        if (tid < 300) {
            hp[tid] = brow + dotreg(w, hs);
        } else if (tid < 400) {
            int j = tid - 300;
            xs[j] = xv0; xs[j + 100] = xv1; xs[j + 200] = xv2;
            if (t + 1 < T_) {
                const float* x = xpb + (size_t)(t + 1) * G3_;
                xv0 = x[j]; xv1 = x[j + 100]; xv2 = x[j + 200];
            }
        } else if (tid < 500) {
            tss[tid - 400] = dotreg(w, ss);
        }
        __syncthreads();

        // ---- P2: GRU elementwise -> h_t ----
        if (tid < 100) {
            float r  = sigmoidf_(xs[tid]       + hp[tid]);
            float z  = sigmoidf_(xs[100 + tid] + hp[100 + tid]);
            float ng = tanhf    (xs[200 + tid] + r * hp[200 + tid]);
            hs[tid] = (1.f - z) * ng + z * hs[tid];
        }
        __syncthreads();

        // ---- P3: W_ti . h_t ; scalar reductions ----
        if (tid >= 300 && tid < 400) {
            tiv[tid - 300] = dotreg(w, hs);
        } else if (wid < 4) {
            float v;
            if (wid == 0) {          // sum(h)
                v = hs[lane] + hs[lane + 32] + hs[lane + 64]
                  + ((lane < 4) ? hs[lane + 96] : 0.f);
            } else if (wid == 1) {   // sum(h^2)
                float a = hs[lane], c = hs[lane + 32], d = hs[lane + 64];
                float e = (lane < 4) ? hs[lane + 96] : 0.f;
                v = a * a + c * c + d * d + e * e;
            } else if (wid == 2) {   // W_lgr[:, :100] . h
                v = WLQ[lane] * hs[lane] + WLQ[lane + 32] * hs[lane + 32]
                  + WLQ[lane + 64] * hs[lane + 64]
                  + ((lane < 4) ? WLQ[lane + 96] * hs[lane + 96] : 0.f);
            } else {                 // W_lgr[:, 100:] . s_{t-1}
                v = WLS[lane] * ss[lane] + WLS[lane + 32] * ss[lane + 32]
                  + WLS[lane + 64] * ss[lane + 64]
                  + ((lane < 4) ? WLS[lane + 96] * ss[lane + 96] : 0.f);
            }
            #pragma unroll
            for (int o = 16; o > 0; o >>= 1) v += __shfl_xor_sync(0xffffffffu, v, o);
            if (lane == 0) scal[wid] = v;
        }
        __syncthreads();

        // ---- P4: second recurrence state update ----
        if (tid < 100) {
            float hsum = scal[0], h2 = scal[1], li = scal[2], wd = scal[3];
            float att  = 0.001f * hsum / fmaxf(sqrtf(h2), 1e-12f);
            float zt   = (t < len) ? fmaxf(att, 0.f) : 0.f;
            float gate = sigmoidf_(li + wd + blgr);
            float ns   = tanhf(tiv[tid] + bti + gate * tss[tid] + bts);
            ss[tid] = (1.f - zt) * ss[tid] + zt * ns;
        }
        __syncthreads();
    }

    // output head: out[b, c] = W_out[c] . state + b_out[c]
    if (tid < NC_) {
        float a = b_out[tid];
        for (int k = 0; k < 100; ++k)
            a = fmaf(W_out[tid * 100 + k], ss[k], a);
        out[b * NC_ + tid] = a;
    }
}

extern "C" void kernel_launch(void* const* d_in, const int* in_sizes, int n_in,
                              void* d_out, int out_size)
{
    const int*   txt   = (const int*)  d_in[0];
    const int*   lens  = (const int*)  d_in[1];
    const float* emb   = (const float*)d_in[2];
    const float* W_ih  = (const float*)d_in[3];
    const float* W_hh  = (const float*)d_in[4];
    const float* b_ih  = (const float*)d_in[5];
    const float* b_hh  = (const float*)d_in[6];
    const float* W_lgr = (const float*)d_in[7];
    const float* b_lgr = (const float*)d_in[8];
    const float* W_ts  = (const float*)d_in[9];
    const float* b_ts  = (const float*)d_in[10];
    const float* W_ti  = (const float*)d_in[11];
    const float* b_ti  = (const float*)d_in[12];
    const float* W_out = (const float*)d_in[13];
    const float* b_out = (const float*)d_in[14];
    float* out = (float*)d_out;

    cudaFuncSetAttribute(xp_kernel,
                         cudaFuncAttributeMaxDynamicSharedMemorySize,
                         A_SMEM_BYTES);

    xp_kernel<<<(B_ * T_) / 32, 256, A_SMEM_BYTES>>>(txt, emb, W_ih, b_ih);
    scan_kernel<<<B_, 512>>>(lens,
                             W_hh, b_hh, W_lgr, b_lgr,
                             W_ts, b_ts, W_ti, b_ti,
                             W_out, b_out, out);
}

// round 5
// speedup vs baseline: 1.2720x; 1.1279x over previous
#include <cuda_runtime.h>
#include <cstdint>
#include <cstddef>

#define B_  256
#define T_  512
#define E_  200
#define H_  100
#define G3_ 300
#define NC_ 5

typedef unsigned long long ull;

// 256*512*300 floats = 157 MB scratch for GRU input preactivations.
__device__ float g_xp[39321600];

// packed fp32x2 FMA / ADD (Blackwell sm_103a); exact per-lane fp32 semantics
#define FMA2(d, a, b, c) \
    asm("fma.rn.f32x2 %0, %1, %2, %3;" : "=l"(d) : "l"(a), "l"(b), "l"(c))
#define ADD2(d, a, b) \
    asm("add.rn.f32x2 %0, %1, %2;" : "=l"(d) : "l"(a), "l"(b))

__device__ __forceinline__ float sigmoidf_(float x) {
    return 1.0f / (1.0f + __expf(-x));
}

__device__ __forceinline__ float sum2(ull v) {
    float a, b_;
    asm("mov.b64 {%0, %1}, %2;" : "=f"(a), "=f"(b_) : "l"(v));
    return a + b_;
}

// ---------------------------------------------------------------------------
// Kernel A: xp[row,:] = scale(row) * (emb[txt[row]] @ W_ih^T) + b_ih
// ---------------------------------------------------------------------------
#define A_ESD_OFF   0                       // float2[32][200] = 51200 B
#define A_WST_OFF   51200                   // float[10][300]  = 12000 B
#define A_SC_OFF    (51200 + 12000)
#define A_N2_OFF    (A_SC_OFF + 128)
#define A_TOK_OFF   (A_N2_OFF + 128)
#define A_SMEM_BYTES (A_TOK_OFF + 128)

__global__ void __launch_bounds__(256) xp_kernel(
    const int* __restrict__ txt, const float* __restrict__ emb,
    const float* __restrict__ W_ih, const float* __restrict__ b_ih)
{
    extern __shared__ char asm_[];
    float2* esd = (float2*)(asm_ + A_ESD_OFF);      // [32][200], dup lanes
    float*  wst = (float*) (asm_ + A_WST_OFF);      // [10][300]
    float*  sc  = (float*) (asm_ + A_SC_OFF);
    float*  n2  = (float*) (asm_ + A_N2_OFF);
    int*    toks= (int*)   (asm_ + A_TOK_OFF);

    const int tid  = threadIdx.x;
    const int row0 = blockIdx.x * 32;

    if (tid < 32) { toks[tid] = txt[row0 + tid]; n2[tid] = 0.f; }
    __syncthreads();

    for (int idx = tid; idx < 32 * 200; idx += 256) {
        int r = idx / 200, k = idx - r * 200;
        float v = emb[(size_t)toks[r] * E_ + k];
        esd[r * 200 + k] = make_float2(v, v);
    }
    __syncthreads();

    if (tid < 128) {
        int r = tid & 31, q = tid >> 5;
        float p = 0.f;
        for (int k = q * 50; k < q * 50 + 50; ++k) {
            float v = esd[r * 200 + k].x;
            p = fmaf(v, v, p);
        }
        atomicAdd(&n2[r], p);
    }
    __syncthreads();
    if (tid < 32) {
        float n = sqrtf(n2[tid]);
        sc[tid] = (n > 1.0f) ? 1.0f / (n + 1e-7f) : 1.0f;
    }
    __syncthreads();

    const int cg = tid % 30;
    const int rg = tid / 30;

    ull acc[4][5];
    #pragma unroll
    for (int i = 0; i < 4; i++)
        #pragma unroll
        for (int j = 0; j < 5; j++) acc[i][j] = 0ull;

    for (int k0 = 0; k0 < 200; k0 += 10) {
        for (int idx = tid; idx < 3000; idx += 256) {
            int c = idx / 10, kk = idx - c * 10;
            wst[kk * 300 + c] = W_ih[c * 200 + k0 + kk];
        }
        __syncthreads();
        if (tid < 240) {
            #pragma unroll
            for (int kk = 0; kk < 10; kk++) {
                ull e0 = *(const ull*)&esd[(rg * 4 + 0) * 200 + k0 + kk];
                ull e1 = *(const ull*)&esd[(rg * 4 + 1) * 200 + k0 + kk];
                ull e2 = *(const ull*)&esd[(rg * 4 + 2) * 200 + k0 + kk];
                ull e3 = *(const ull*)&esd[(rg * 4 + 3) * 200 + k0 + kk];
                const ull* wr = (const ull*)&wst[kk * 300 + cg * 10];
                #pragma unroll
                for (int j = 0; j < 5; j++) {
                    ull w = wr[j];
                    FMA2(acc[0][j], e0, w, acc[0][j]);
                    FMA2(acc[1][j], e1, w, acc[1][j]);
                    FMA2(acc[2][j], e2, w, acc[2][j]);
                    FMA2(acc[3][j], e3, w, acc[3][j]);
                }
            }
        }
        __syncthreads();
    }

    if (tid < 240) {
        float2 bih[5];
        const float2* bih2 = (const float2*)b_ih;
        #pragma unroll
        for (int j = 0; j < 5; j++) bih[j] = bih2[cg * 5 + j];
        #pragma unroll
        for (int i = 0; i < 4; i++) {
            int r = rg * 4 + i;
            float s = sc[r];
            float2* outp = (float2*)(g_xp + (size_t)(row0 + r) * G3_ + cg * 10);
            #pragma unroll
            for (int j = 0; j < 5; j++) {
                float2 a = *(float2*)&acc[i][j];
                float2 v;
                v.x = fmaf(s, a.x, bih[j].x);
                v.y = fmaf(s, a.y, bih[j].y);
                outp[j] = v;
            }
        }
    }
}

// ---------------------------------------------------------------------------
// Kernel B: fused scan. 256 threads/CTA, TWO weight rows per thread so the
// 200 weight registers fit comfortably under the 255-reg/thread cap (no
// spills). Row ownership:
//   tid   0-149 : W_hh rows 2*tid, 2*tid+1          (phase 1)
//   tid 150-199 : W_ti rows 2*(tid-150)+{0,1}       (phase 3; stages xp in P1)
//   tid 200-249 : W_ts rows 2*(tid-200)+{0,1}       (phase 1)
//   warps 0-3   : scalar reductions in phase 3 (their dot work is phase 1)
// ---------------------------------------------------------------------------
__device__ __forceinline__ void dot2(const ull* __restrict__ wA,
                                     const ull* __restrict__ wB,
                                     const float* __restrict__ v,
                                     float& rA, float& rB)
{
    const ulonglong2* h4 = (const ulonglong2*)v;   // 16B-aligned smem
    ull aA0 = 0ull, aA1 = 0ull, aB0 = 0ull, aB1 = 0ull;
    #pragma unroll
    for (int i = 0; i < 25; i++) {
        ulonglong2 h = h4[i];
        FMA2(aA0, wA[2 * i],     h.x, aA0);
        FMA2(aA1, wA[2 * i + 1], h.y, aA1);
        FMA2(aB0, wB[2 * i],     h.x, aB0);
        FMA2(aB1, wB[2 * i + 1], h.y, aB1);
    }
    ull tA, tB;
    ADD2(tA, aA0, aA1);
    ADD2(tB, aB0, aB1);
    rA = sum2(tA);
    rB = sum2(tB);
}

__global__ void __launch_bounds__(256, 1) scan_kernel(
    const int*   __restrict__ lens,
    const float* __restrict__ W_hh, const float* __restrict__ b_hh,
    const float* __restrict__ W_lgr, const float* __restrict__ b_lgr,
    const float* __restrict__ W_ts, const float* __restrict__ b_ts,
    const float* __restrict__ W_ti, const float* __restrict__ b_ti,
    const float* __restrict__ W_out, const float* __restrict__ b_out,
    float* __restrict__ out)
{
    __shared__ __align__(16) float hs[100];
    __shared__ __align__(16) float ss[100];
    __shared__ __align__(16) float hp[300];
    __shared__ __align__(16) float xs[300];
    __shared__ __align__(16) float tiv[100];
    __shared__ __align__(16) float tss[100];
    __shared__ __align__(16) float WLQ[100];
    __shared__ __align__(16) float WLS[100];
    __shared__ float scal[4];

    const int tid = threadIdx.x;
    const int b   = blockIdx.x;

    // ---- per-thread weight rows -> registers (2 x 50 f32x2) ----
    const float* pA;
    float browA = 0.f, browB = 0.f;
    if (tid < 150) {
        pA = W_hh + (size_t)(2 * tid) * 100;
        browA = b_hh[2 * tid];
        browB = b_hh[2 * tid + 1];
    } else if (tid < 200) {
        pA = W_ti + (size_t)(2 * (tid - 150)) * 100;
    } else if (tid < 250) {
        pA = W_ts + (size_t)(2 * (tid - 200)) * 100;
    } else {
        pA = W_hh;   // dummy (never used in dots)
    }
    ull wA[50], wB[50];
    {
        const ull* a = (const ull*)pA;          // rows are 400B apart: aligned
        const ull* b2 = (const ull*)(pA + 100);
        #pragma unroll
        for (int i = 0; i < 50; i++) { wA[i] = a[i]; wB[i] = b2[i]; }
    }

    if (tid < 100) {
        WLQ[tid] = W_lgr[tid];
        WLS[tid] = W_lgr[100 + tid];
        hs[tid]  = 0.f;
        ss[tid]  = 0.f;
    }
    float bts = 0.f, bti = 0.f;
    if (tid < 100) { bts = b_ts[tid]; bti = b_ti[tid]; }
    const float blgr = b_lgr[0];
    const int   len  = lens[b];

    const float* xpb = g_xp + (size_t)b * T_ * G3_;
    float xv[6];
    if (tid >= 150 && tid < 200) {             // prefetch t=0
        int j = tid - 150;
        #pragma unroll
        for (int q = 0; q < 6; q++) xv[q] = xpb[j + 50 * q];
    }
    __syncthreads();

    const int wid  = tid >> 5;
    const int lane = tid & 31;

    for (int t = 0; t < T_; ++t) {
        // ---- P1: dots on h_{t-1}, s_{t-1}; xp staging + prefetch ----
        if (tid < 150) {
            float rA, rB;
            dot2(wA, wB, hs, rA, rB);
            hp[2 * tid]     = browA + rA;
            hp[2 * tid + 1] = browB + rB;
        } else if (tid < 200) {
            int j = tid - 150;
            #pragma unroll
            for (int q = 0; q < 6; q++) xs[j + 50 * q] = xv[q];
            if (t + 1 < T_) {
                const float* x = xpb + (size_t)(t + 1) * G3_;
                #pragma unroll
                for (int q = 0; q < 6; q++) xv[q] = x[j + 50 * q];
            }
        } else if (tid < 250) {
            float rA, rB;
            dot2(wA, wB, ss, rA, rB);
            int j = tid - 200;
            tss[2 * j]     = rA;
            tss[2 * j + 1] = rB;
        }
        __syncthreads();

        // ---- P2: GRU elementwise -> h_t ----
        if (tid < 100) {
            float r  = sigmoidf_(xs[tid]       + hp[tid]);
            float z  = sigmoidf_(xs[100 + tid] + hp[100 + tid]);
            float ng = tanhf    (xs[200 + tid] + r * hp[200 + tid]);
            hs[tid] = (1.f - z) * ng + z * hs[tid];
        }
        __syncthreads();

        // ---- P3: W_ti . h_t ; scalar reductions (warps 0-3 are free) ----
        if (tid >= 150 && tid < 200) {
            float rA, rB;
            dot2(wA, wB, hs, rA, rB);
            int j = tid - 150;
            tiv[2 * j]     = rA;
            tiv[2 * j + 1] = rB;
        } else if (wid < 4) {
            float v;
            if (wid == 0) {          // sum(h)
                v = hs[lane] + hs[lane + 32] + hs[lane + 64]
                  + ((lane < 4) ? hs[lane + 96] : 0.f);
            } else if (wid == 1) {   // sum(h^2)
                float a = hs[lane], c = hs[lane + 32], d = hs[lane + 64];
                float e = (lane < 4) ? hs[lane + 96] : 0.f;
                v = a * a + c * c + d * d + e * e;
            } else if (wid == 2) {   // W_lgr[:, :100] . h
                v = WLQ[lane] * hs[lane] + WLQ[lane + 32] * hs[lane + 32]
                  + WLQ[lane + 64] * hs[lane + 64]
                  + ((lane < 4) ? WLQ[lane + 96] * hs[lane + 96] : 0.f);
            } else {                 // W_lgr[:, 100:] . s_{t-1}
                v = WLS[lane] * ss[lane] + WLS[lane + 32] * ss[lane + 32]
                  + WLS[lane + 64] * ss[lane + 64]
                  + ((lane < 4) ? WLS[lane + 96] * ss[lane + 96] : 0.f);
            }
            #pragma unroll
            for (int o = 16; o > 0; o >>= 1) v += __shfl_xor_sync(0xffffffffu, v, o);
            if (lane == 0) scal[wid] = v;
        }
        __syncthreads();

        // ---- P4: second recurrence state update ----
        if (tid < 100) {
            float hsum = scal[0], h2 = scal[1], li = scal[2], wd = scal[3];
            float att  = 0.001f * hsum / fmaxf(sqrtf(h2), 1e-12f);
            float zt   = (t < len) ? fmaxf(att, 0.f) : 0.f;
            float gate = sigmoidf_(li + wd + blgr);
            float ns   = tanhf(tiv[tid] + bti + gate * tss[tid] + bts);
            ss[tid] = (1.f - zt) * ss[tid] + zt * ns;
        }
        __syncthreads();
    }

    // output head: out[b, c] = W_out[c] . state + b_out[c]
    if (tid < NC_) {
        float a = b_out[tid];
        for (int k = 0; k < 100; ++k)
            a = fmaf(W_out[tid * 100 + k], ss[k], a);
        out[b * NC_ + tid] = a;
    }
}

extern "C" void kernel_launch(void* const* d_in, const int* in_sizes, int n_in,
                              void* d_out, int out_size)
{
    const int*   txt   = (const int*)  d_in[0];
    const int*   lens  = (const int*)  d_in[1];
    const float* emb   = (const float*)d_in[2];
    const float* W_ih  = (const float*)d_in[3];
    const float* W_hh  = (const float*)d_in[4];
    const float* b_ih  = (const float*)d_in[5];
    const float* b_hh  = (const float*)d_in[6];
    const float* W_lgr = (const float*)d_in[7];
    const float* b_lgr = (const float*)d_in[8];
    const float* W_ts  = (const float*)d_in[9];
    const float* b_ts  = (const float*)d_in[10];
    const float* W_ti  = (const float*)d_in[11];
    const float* b_ti  = (const float*)d_in[12];
    const float* W_out = (const float*)d_in[13];
    const float* b_out = (const float*)d_in[14];
    float* out = (float*)d_out;

    cudaFuncSetAttribute(xp_kernel,
                         cudaFuncAttributeMaxDynamicSharedMemorySize,
                         A_SMEM_BYTES);

    xp_kernel<<<(B_ * T_) / 32, 256, A_SMEM_BYTES>>>(txt, emb, W_ih, b_ih);
    scan_kernel<<<B_, 256>>>(lens,
                             W_hh, b_hh, W_lgr, b_lgr,
                             W_ts, b_ts, W_ti, b_ti,
                             W_out, b_out, out);
}

// round 6
// speedup vs baseline: 1.6705x; 1.3133x over previous
#include <cuda_runtime.h>
#include <cstdint>
#include <cstddef>

#define B_  256
#define T_  512
#define E_  200
#define H_  100
#define G3_ 300
#define NC_ 5

typedef unsigned long long ull;

// 256*512*300 floats = 157 MB scratch for GRU input preactivations.
__device__ float g_xp[39321600];

// packed fp32x2 FMA / ADD (Blackwell sm_103a); exact per-lane fp32 semantics
#define FMA2(d, a, b, c) \
    asm("fma.rn.f32x2 %0, %1, %2, %3;" : "=l"(d) : "l"(a), "l"(b), "l"(c))
#define ADD2(d, a, b) \
    asm("add.rn.f32x2 %0, %1, %2;" : "=l"(d) : "l"(a), "l"(b))

__device__ __forceinline__ float sigmoidf_(float x) {
    return 1.0f / (1.0f + __expf(-x));
}

__device__ __forceinline__ float sum2(ull v) {
    float a, b_;
    asm("mov.b64 {%0, %1}, %2;" : "=f"(a), "=f"(b_) : "l"(v));
    return a + b_;
}

__device__ __forceinline__ uint32_t s2u(const void* p) {
    return (uint32_t)__cvta_generic_to_shared(p);
}

// ---------------------------------------------------------------------------
// Kernel A: xp[row,:] = scale(row) * (emb[txt[row]] @ W_ih^T) + b_ih
// (unchanged from R5 — isolate the scan restructure)
// ---------------------------------------------------------------------------
#define A_ESD_OFF   0                       // float2[32][200] = 51200 B
#define A_WST_OFF   51200                   // float[10][300]  = 12000 B
#define A_SC_OFF    (51200 + 12000)
#define A_N2_OFF    (A_SC_OFF + 128)
#define A_TOK_OFF   (A_N2_OFF + 128)
#define A_SMEM_BYTES (A_TOK_OFF + 128)

__global__ void __launch_bounds__(256) xp_kernel(
    const int* __restrict__ txt, const float* __restrict__ emb,
    const float* __restrict__ W_ih, const float* __restrict__ b_ih)
{
    extern __shared__ char asm_[];
    float2* esd = (float2*)(asm_ + A_ESD_OFF);
    float*  wst = (float*) (asm_ + A_WST_OFF);
    float*  sc  = (float*) (asm_ + A_SC_OFF);
    float*  n2  = (float*) (asm_ + A_N2_OFF);
    int*    toks= (int*)   (asm_ + A_TOK_OFF);

    const int tid  = threadIdx.x;
    const int row0 = blockIdx.x * 32;

    if (tid < 32) { toks[tid] = txt[row0 + tid]; n2[tid] = 0.f; }
    __syncthreads();

    for (int idx = tid; idx < 32 * 200; idx += 256) {
        int r = idx / 200, k = idx - r * 200;
        float v = emb[(size_t)toks[r] * E_ + k];
        esd[r * 200 + k] = make_float2(v, v);
    }
    __syncthreads();

    if (tid < 128) {
        int r = tid & 31, q = tid >> 5;
        float p = 0.f;
        for (int k = q * 50; k < q * 50 + 50; ++k) {
            float v = esd[r * 200 + k].x;
            p = fmaf(v, v, p);
        }
        atomicAdd(&n2[r], p);
    }
    __syncthreads();
    if (tid < 32) {
        float n = sqrtf(n2[tid]);
        sc[tid] = (n > 1.0f) ? 1.0f / (n + 1e-7f) : 1.0f;
    }
    __syncthreads();

    const int cg = tid % 30;
    const int rg = tid / 30;

    ull acc[4][5];
    #pragma unroll
    for (int i = 0; i < 4; i++)
        #pragma unroll
        for (int j = 0; j < 5; j++) acc[i][j] = 0ull;

    for (int k0 = 0; k0 < 200; k0 += 10) {
        for (int idx = tid; idx < 3000; idx += 256) {
            int c = idx / 10, kk = idx - c * 10;
            wst[kk * 300 + c] = W_ih[c * 200 + k0 + kk];
        }
        __syncthreads();
        if (tid < 240) {
            #pragma unroll
            for (int kk = 0; kk < 10; kk++) {
                ull e0 = *(const ull*)&esd[(rg * 4 + 0) * 200 + k0 + kk];
                ull e1 = *(const ull*)&esd[(rg * 4 + 1) * 200 + k0 + kk];
                ull e2 = *(const ull*)&esd[(rg * 4 + 2) * 200 + k0 + kk];
                ull e3 = *(const ull*)&esd[(rg * 4 + 3) * 200 + k0 + kk];
                const ull* wr = (const ull*)&wst[kk * 300 + cg * 10];
                #pragma unroll
                for (int j = 0; j < 5; j++) {
                    ull w = wr[j];
                    FMA2(acc[0][j], e0, w, acc[0][j]);
                    FMA2(acc[1][j], e1, w, acc[1][j]);
                    FMA2(acc[2][j], e2, w, acc[2][j]);
                    FMA2(acc[3][j], e3, w, acc[3][j]);
                }
            }
        }
        __syncthreads();
    }

    if (tid < 240) {
        float2 bih[5];
        const float2* bih2 = (const float2*)b_ih;
        #pragma unroll
        for (int j = 0; j < 5; j++) bih[j] = bih2[cg * 5 + j];
        #pragma unroll
        for (int i = 0; i < 4; i++) {
            int r = rg * 4 + i;
            float s = sc[r];
            float2* outp = (float2*)(g_xp + (size_t)(row0 + r) * G3_ + cg * 10);
            #pragma unroll
            for (int j = 0; j < 5; j++) {
                float2 a = *(float2*)&acc[i][j];
                float2 v;
                v.x = fmaf(s, a.x, bih[j].x);
                v.y = fmaf(s, a.y, bih[j].y);
                outp[j] = v;
            }
        }
    }
}

// ---------------------------------------------------------------------------
// Kernel B: fused scan, 2 barriers/step, pipelined second recurrence.
//
// Iteration t (t = 0..512):
//   Stage 1 (all dot rows concurrently; unified code path):
//     hp   = W_hh . h_{t-1} + b_hh   (rows 0-299,   vec=hs, active t<512)
//     tiv  = W_ti . h_{t-1}          (rows 300-399, vec=hs, active t>=1)
//     tss  = W_ts . s_{t-2}          (rows 400-499, vec=ss, active t>=1)
//     scal[2]=WLQ.h, scal[0]=sum(h)  (tid 250: rows WLQ, ones; vec=hs)
//     scal[3]=WLS.s (+0-row)         (tid 251, vec=ss)
//     scal[1]=h.h                    (tid 252, special)
//     h-threads (0-99) also prefetch xp[t+1] into registers.
//   Stage 2:
//     tid 0-99   : h_t  = GRU(xp[t], hp, h_{t-1})          (t<512)
//     tid 128-227: s_{t-1} update from tiv/tss/scal        (t>=1)
// ---------------------------------------------------------------------------
__global__ void __launch_bounds__(256, 1) scan_kernel(
    const int*   __restrict__ lens,
    const float* __restrict__ W_hh, const float* __restrict__ b_hh,
    const float* __restrict__ W_lgr, const float* __restrict__ b_lgr,
    const float* __restrict__ W_ts, const float* __restrict__ b_ts,
    const float* __restrict__ W_ti, const float* __restrict__ b_ti,
    const float* __restrict__ W_out, const float* __restrict__ b_out,
    float* __restrict__ out)
{
    __shared__ __align__(16) float hs[100];
    __shared__ __align__(16) float ss[100];
    __shared__ __align__(16) float hp[300];
    __shared__ __align__(16) float tiv[100];
    __shared__ __align__(16) float tss[100];
    __shared__ __align__(16) float scal[4];
    __shared__ __align__(16) float dummy[4];

    const int tid = threadIdx.x;
    const int b   = blockIdx.x;

    // ---- unified dot-thread setup ----
    // mode 0: standard dot2; mode 1: sumsq(h); mode 2: idle
    int   mode  = 2;
    int   hhRow = 0;           // 1 if this thread's rows depend on t<512 (W_hh)
    const float* wpA = W_hh;   // global row A (row B = wpA+100 when fromMem)
    int   fromMem = 1;         // wB from memory (else constant fill)
    float wBconst = 0.f;
    float biasA = 0.f, biasB = 0.f;
    uint32_t vOff = s2u(hs), outAOff = s2u(dummy), outBOff = s2u(dummy + 1);

    const int r = 2 * tid;
    if (tid < 150) {                 // W_hh rows r, r+1
        mode = 0; hhRow = 1;
        wpA = W_hh + (size_t)r * 100;
        biasA = b_hh[r]; biasB = b_hh[r + 1];
        vOff = s2u(hs);
        outAOff = s2u(hp + r); outBOff = s2u(hp + r + 1);
    } else if (tid < 200) {          // W_ti rows r-300
        mode = 0;
        wpA = W_ti + (size_t)(r - 300) * 100;
        vOff = s2u(hs);
        outAOff = s2u(tiv + (r - 300)); outBOff = s2u(tiv + (r - 299));
    } else if (tid < 250) {          // W_ts rows r-400
        mode = 0;
        wpA = W_ts + (size_t)(r - 400) * 100;
        vOff = s2u(ss);
        outAOff = s2u(tss + (r - 400)); outBOff = s2u(tss + (r - 399));
    } else if (tid == 250) {         // WLQ.h -> scal[2], sum(h) -> scal[0]
        mode = 0;
        wpA = W_lgr;                 // first 100 = WLQ
        fromMem = 0; wBconst = 1.0f; // row B = ones
        vOff = s2u(hs);
        outAOff = s2u(scal + 2); outBOff = s2u(scal + 0);
    } else if (tid == 251) {         // WLS.s -> scal[3]
        mode = 0;
        wpA = W_lgr + 100;
        fromMem = 0; wBconst = 0.0f;
        vOff = s2u(ss);
        outAOff = s2u(scal + 3); outBOff = s2u(dummy + 2);
    } else if (tid == 252) {         // h.h -> scal[1]
        mode = 1;
        vOff = s2u(hs);
        outAOff = s2u(scal + 1);
    }

    ull wA[50], wB[50];
    {
        const ull* a  = (const ull*)wpA;
        const ull* b2 = (const ull*)(wpA + 100);
        float2 cst = make_float2(wBconst, wBconst);
        ull cstu = *(ull*)&cst;
        #pragma unroll
        for (int i = 0; i < 50; i++) {
            wA[i] = a[i];
            wB[i] = fromMem ? b2[i] : cstu;
        }
    }

    // state init
    float hreg = 0.f, sreg = 0.f;
    if (tid < 100) hs[tid] = 0.f;
    if (tid < 100) ss[tid] = 0.f;

    float bti = 0.f, bts = 0.f;
    if (tid >= 128 && tid < 228) { bti = b_ti[tid - 128]; bts = b_ts[tid - 128]; }
    const float blgr = b_lgr[0];
    const int   len  = lens[b];

    const float* xpb = g_xp + (size_t)b * T_ * G3_;
    float xv0 = 0.f, xv1 = 0.f, xv2 = 0.f;   // xp[t]
    float xn0 = 0.f, xn1 = 0.f, xn2 = 0.f;   // xp[t+1]
    if (tid < 100) {
        xv0 = xpb[tid]; xv1 = xpb[100 + tid]; xv2 = xpb[200 + tid];
    }
    __syncthreads();

    for (int t = 0; t <= T_; ++t) {
        // ---------------- Stage 1 ----------------
        // prefetch xp[t+1] (h-threads; issued before the dot)
        if (tid < 100 && t + 1 < T_) {
            const float* x = xpb + (size_t)(t + 1) * G3_;
            xn0 = x[tid]; xn1 = x[100 + tid]; xn2 = x[200 + tid];
        }

        const bool act = mode == 0 ? (hhRow ? (t < T_) : (t >= 1))
                                   : (mode == 1 && t >= 1);
        if (mode == 0 && act) {
            ull a0 = 0ull, a1 = 0ull, b0 = 0ull, b1 = 0ull;
            #pragma unroll
            for (int i = 0; i < 25; i++) {
                ull hx, hy;
                asm volatile("ld.shared.v2.b64 {%0, %1}, [%2];"
                             : "=l"(hx), "=l"(hy) : "r"(vOff + i * 16));
                FMA2(a0, wA[2 * i],     hx, a0);
                FMA2(a1, wA[2 * i + 1], hy, a1);
                FMA2(b0, wB[2 * i],     hx, b0);
                FMA2(b1, wB[2 * i + 1], hy, b1);
            }
            ull ta, tb;
            ADD2(ta, a0, a1);
            ADD2(tb, b0, b1);
            float rA = sum2(ta) + biasA;
            float rB = sum2(tb) + biasB;
            asm volatile("st.shared.f32 [%0], %1;" :: "r"(outAOff), "f"(rA));
            asm volatile("st.shared.f32 [%0], %1;" :: "r"(outBOff), "f"(rB));
        } else if (mode == 1 && act) {
            ull a0 = 0ull, a1 = 0ull;
            #pragma unroll
            for (int i = 0; i < 25; i++) {
                ull hx, hy;
                asm volatile("ld.shared.v2.b64 {%0, %1}, [%2];"
                             : "=l"(hx), "=l"(hy) : "r"(vOff + i * 16));
                FMA2(a0, hx, hx, a0);
                FMA2(a1, hy, hy, a1);
            }
            ull ta;
            ADD2(ta, a0, a1);
            float rA = sum2(ta);
            asm volatile("st.shared.f32 [%0], %1;" :: "r"(outAOff), "f"(rA));
        }
        __syncthreads();

        // ---------------- Stage 2 ----------------
        if (tid < 100) {
            if (t < T_) {
                float rr = sigmoidf_(xv0 + hp[tid]);
                float z  = sigmoidf_(xv1 + hp[100 + tid]);
                float ng = tanhf    (xv2 + rr * hp[200 + tid]);
                hreg = (1.f - z) * ng + z * hreg;
                hs[tid] = hreg;
                xv0 = xn0; xv1 = xn1; xv2 = xn2;
            }
        } else if (tid >= 128 && tid < 228) {
            if (t >= 1) {
                int i = tid - 128;
                float hsum = scal[0], h2 = scal[1], li = scal[2], wd = scal[3];
                float att  = 0.001f * hsum / fmaxf(sqrtf(h2), 1e-12f);
                float zt   = (t - 1 < len) ? fmaxf(att, 0.f) : 0.f;
                float gate = sigmoidf_(li + wd + blgr);
                float ns   = tanhf(tiv[i] + bti + gate * tss[i] + bts);
                sreg = (1.f - zt) * sreg + zt * ns;
                ss[i] = sreg;
            }
        }
        __syncthreads();
    }

    // output head: out[b, c] = W_out[c] . state + b_out[c]
    if (tid < NC_) {
        float a = b_out[tid];
        for (int k = 0; k < 100; ++k)
            a = fmaf(W_out[tid * 100 + k], ss[k], a);
        out[b * NC_ + tid] = a;
    }
}

extern "C" void kernel_launch(void* const* d_in, const int* in_sizes, int n_in,
                              void* d_out, int out_size)
{
    const int*   txt   = (const int*)  d_in[0];
    const int*   lens  = (const int*)  d_in[1];
    const float* emb   = (const float*)d_in[2];
    const float* W_ih  = (const float*)d_in[3];
    const float* W_hh  = (const float*)d_in[4];
    const float* b_ih  = (const float*)d_in[5];
    const float* b_hh  = (const float*)d_in[6];
    const float* W_lgr = (const float*)d_in[7];
    const float* b_lgr = (const float*)d_in[8];
    const float* W_ts  = (const float*)d_in[9];
    const float* b_ts  = (const float*)d_in[10];
    const float* W_ti  = (const float*)d_in[11];
    const float* b_ti  = (const float*)d_in[12];
    const float* W_out = (const float*)d_in[13];
    const float* b_out = (const float*)d_in[14];
    float* out = (float*)d_out;

    cudaFuncSetAttribute(xp_kernel,
                         cudaFuncAttributeMaxDynamicSharedMemorySize,
                         A_SMEM_BYTES);

    xp_kernel<<<(B_ * T_) / 32, 256, A_SMEM_BYTES>>>(txt, emb, W_ih, b_ih);
    scan_kernel<<<B_, 256>>>(lens,
                             W_hh, b_hh, W_lgr, b_lgr,
                             W_ts, b_ts, W_ti, b_ti,
                             W_out, b_out, out);
}

// round 7
// speedup vs baseline: 1.7177x; 1.0283x over previous
#include <cuda_runtime.h>
#include <cstdint>
#include <cstddef>

#define B_  256
#define T_  512
#define E_  200
#define H_  100
#define G3_ 300
#define NC_ 5

typedef unsigned long long ull;

// 256*512*300 floats = 157 MB scratch for GRU input preactivations.
__device__ float g_xp[39321600];

// packed fp32x2 FMA / ADD (Blackwell sm_103a); exact per-lane fp32 semantics
#define FMA2(d, a, b, c) \
    asm("fma.rn.f32x2 %0, %1, %2, %3;" : "=l"(d) : "l"(a), "l"(b), "l"(c))
#define ADD2(d, a, b) \
    asm("add.rn.f32x2 %0, %1, %2;" : "=l"(d) : "l"(a), "l"(b))

__device__ __forceinline__ float sigmoidf_(float x) {
    return 1.0f / (1.0f + __expf(-x));
}

__device__ __forceinline__ float sum2(ull v) {
    float a, b_;
    asm("mov.b64 {%0, %1}, %2;" : "=f"(a), "=f"(b_) : "l"(v));
    return a + b_;
}

__device__ __forceinline__ uint32_t s2u(const void* p) {
    return (uint32_t)__cvta_generic_to_shared(p);
}

// ---------------------------------------------------------------------------
// Kernel A: xp[row,:] = scale(row) * (emb[txt[row]] @ W_ih^T) + b_ih
// (unchanged — isolate the scan change)
// ---------------------------------------------------------------------------
#define A_ESD_OFF   0
#define A_WST_OFF   51200
#define A_SC_OFF    (51200 + 12000)
#define A_N2_OFF    (A_SC_OFF + 128)
#define A_TOK_OFF   (A_N2_OFF + 128)
#define A_SMEM_BYTES (A_TOK_OFF + 128)

__global__ void __launch_bounds__(256) xp_kernel(
    const int* __restrict__ txt, const float* __restrict__ emb,
    const float* __restrict__ W_ih, const float* __restrict__ b_ih)
{
    extern __shared__ char asm_[];
    float2* esd = (float2*)(asm_ + A_ESD_OFF);
    float*  wst = (float*) (asm_ + A_WST_OFF);
    float*  sc  = (float*) (asm_ + A_SC_OFF);
    float*  n2  = (float*) (asm_ + A_N2_OFF);
    int*    toks= (int*)   (asm_ + A_TOK_OFF);

    const int tid  = threadIdx.x;
    const int row0 = blockIdx.x * 32;

    if (tid < 32) { toks[tid] = txt[row0 + tid]; n2[tid] = 0.f; }
    __syncthreads();

    for (int idx = tid; idx < 32 * 200; idx += 256) {
        int r = idx / 200, k = idx - r * 200;
        float v = emb[(size_t)toks[r] * E_ + k];
        esd[r * 200 + k] = make_float2(v, v);
    }
    __syncthreads();

    if (tid < 128) {
        int r = tid & 31, q = tid >> 5;
        float p = 0.f;
        for (int k = q * 50; k < q * 50 + 50; ++k) {
            float v = esd[r * 200 + k].x;
            p = fmaf(v, v, p);
        }
        atomicAdd(&n2[r], p);
    }
    __syncthreads();
    if (tid < 32) {
        float n = sqrtf(n2[tid]);
        sc[tid] = (n > 1.0f) ? 1.0f / (n + 1e-7f) : 1.0f;
    }
    __syncthreads();

    const int cg = tid % 30;
    const int rg = tid / 30;

    ull acc[4][5];
    #pragma unroll
    for (int i = 0; i < 4; i++)
        #pragma unroll
        for (int j = 0; j < 5; j++) acc[i][j] = 0ull;

    for (int k0 = 0; k0 < 200; k0 += 10) {
        for (int idx = tid; idx < 3000; idx += 256) {
            int c = idx / 10, kk = idx - c * 10;
            wst[kk * 300 + c] = W_ih[c * 200 + k0 + kk];
        }
        __syncthreads();
        if (tid < 240) {
            #pragma unroll
            for (int kk = 0; kk < 10; kk++) {
                ull e0 = *(const ull*)&esd[(rg * 4 + 0) * 200 + k0 + kk];
                ull e1 = *(const ull*)&esd[(rg * 4 + 1) * 200 + k0 + kk];
                ull e2 = *(const ull*)&esd[(rg * 4 + 2) * 200 + k0 + kk];
                ull e3 = *(const ull*)&esd[(rg * 4 + 3) * 200 + k0 + kk];
                const ull* wr = (const ull*)&wst[kk * 300 + cg * 10];
                #pragma unroll
                for (int j = 0; j < 5; j++) {
                    ull w = wr[j];
                    FMA2(acc[0][j], e0, w, acc[0][j]);
                    FMA2(acc[1][j], e1, w, acc[1][j]);
                    FMA2(acc[2][j], e2, w, acc[2][j]);
                    FMA2(acc[3][j], e3, w, acc[3][j]);
                }
            }
        }
        __syncthreads();
    }

    if (tid < 240) {
        float2 bih[5];
        const float2* bih2 = (const float2*)b_ih;
        #pragma unroll
        for (int j = 0; j < 5; j++) bih[j] = bih2[cg * 5 + j];
        #pragma unroll
        for (int i = 0; i < 4; i++) {
            int r = rg * 4 + i;
            float s = sc[r];
            float2* outp = (float2*)(g_xp + (size_t)(row0 + r) * G3_ + cg * 10);
            #pragma unroll
            for (int j = 0; j < 5; j++) {
                float2 a = *(float2*)&acc[i][j];
                float2 v;
                v.x = fmaf(s, a.x, bih[j].x);
                v.y = fmaf(s, a.y, bih[j].y);
                outp[j] = v;
            }
        }
    }
}

// ---------------------------------------------------------------------------
// Kernel B: fused scan, TWO batch elements per CTA sharing one set of
// register-resident weights. Grid = 128 CTAs -> exactly 1 wave.
//
// Stage 1 (iteration t): every dot thread computes its two weight rows
// against BOTH batches' vectors (8 interleaved FMA2 chains):
//   tid   0-149 : W_hh rows          vs hs0/hs1   (act t<512)  -> hp0/hp1
//   tid 150-199 : W_ti rows          vs hs0/hs1   (act t>=1)   -> tiv0/tiv1
//   tid 200-249 : W_ts rows          vs ss0/ss1   (act t>=1)   -> tss0/tss1
//   tid 250     : WLQ rows + ones    vs hs0/hs1   (act t>=1)   -> scal*[2],[0]
//   tid 251     : WLS rows + zeros   vs ss0/ss1   (act t>=1)   -> scal*[3]
//   tid 252/253 : sumsq(h) batch 0/1 (act t>=1)   -> scal*[1]
//   tid 0-199 also prefetch their batch's xp[t+1] (3 LDG each).
// Stage 2: tid 0-99 batch0 / tid 100-199 batch1: GRU h-update (t<512)
//          then second-recurrence s-update (t>=1), both in-thread.
// ---------------------------------------------------------------------------
__global__ void __launch_bounds__(256, 1) scan_kernel(
    const int*   __restrict__ lens,
    const float* __restrict__ W_hh, const float* __restrict__ b_hh,
    const float* __restrict__ W_lgr, const float* __restrict__ b_lgr,
    const float* __restrict__ W_ts, const float* __restrict__ b_ts,
    const float* __restrict__ W_ti, const float* __restrict__ b_ti,
    const float* __restrict__ W_out, const float* __restrict__ b_out,
    float* __restrict__ out)
{
    __shared__ __align__(16) float hs0[100], hs1[100];
    __shared__ __align__(16) float ss0[100], ss1[100];
    __shared__ __align__(16) float hp0[300], hp1[300];
    __shared__ __align__(16) float tiv0[100], tiv1[100];
    __shared__ __align__(16) float tss0[100], tss1[100];
    __shared__ __align__(16) float scal0[4], scal1[4];
    __shared__ __align__(16) float dummy[8];

    const int tid = threadIdx.x;
    const int b0  = blockIdx.x * 2;

    // ---- unified dot-thread setup ----
    int   mode  = 2;                 // 0: dot, 1: sumsq, 2: idle
    int   hhRow = 0;
    const float* wpA = W_hh;
    int   fromMem = 1;
    float wBconst = 0.f;
    float biasA = 0.f, biasB = 0.f;
    uint32_t v0  = s2u(hs0), v1  = s2u(hs1);
    uint32_t oA0 = s2u(dummy), oB0 = s2u(dummy + 1);
    uint32_t oA1 = s2u(dummy + 2), oB1 = s2u(dummy + 3);

    const int r = 2 * tid;
    if (tid < 150) {                 // W_hh rows r, r+1
        mode = 0; hhRow = 1;
        wpA = W_hh + (size_t)r * 100;
        biasA = b_hh[r]; biasB = b_hh[r + 1];
        v0 = s2u(hs0); v1 = s2u(hs1);
        oA0 = s2u(hp0 + r); oB0 = s2u(hp0 + r + 1);
        oA1 = s2u(hp1 + r); oB1 = s2u(hp1 + r + 1);
    } else if (tid < 200) {          // W_ti rows r-300
        mode = 0;
        wpA = W_ti + (size_t)(r - 300) * 100;
        v0 = s2u(hs0); v1 = s2u(hs1);
        oA0 = s2u(tiv0 + (r - 300)); oB0 = s2u(tiv0 + (r - 299));
        oA1 = s2u(tiv1 + (r - 300)); oB1 = s2u(tiv1 + (r - 299));
    } else if (tid < 250) {          // W_ts rows r-400
        mode = 0;
        wpA = W_ts + (size_t)(r - 400) * 100;
        v0 = s2u(ss0); v1 = s2u(ss1);
        oA0 = s2u(tss0 + (r - 400)); oB0 = s2u(tss0 + (r - 399));
        oA1 = s2u(tss1 + (r - 400)); oB1 = s2u(tss1 + (r - 399));
    } else if (tid == 250) {         // WLQ.h -> scal[2]; sum(h) -> scal[0]
        mode = 0;
        wpA = W_lgr;
        fromMem = 0; wBconst = 1.0f;
        v0 = s2u(hs0); v1 = s2u(hs1);
        oA0 = s2u(scal0 + 2); oB0 = s2u(scal0 + 0);
        oA1 = s2u(scal1 + 2); oB1 = s2u(scal1 + 0);
    } else if (tid == 251) {         // WLS.s -> scal[3]
        mode = 0;
        wpA = W_lgr + 100;
        fromMem = 0; wBconst = 0.0f;
        v0 = s2u(ss0); v1 = s2u(ss1);
        oA0 = s2u(scal0 + 3); oB0 = s2u(dummy + 4);
        oA1 = s2u(scal1 + 3); oB1 = s2u(dummy + 5);
    } else if (tid == 252) {         // h0.h0 -> scal0[1]
        mode = 1;
        v0 = s2u(hs0);
        oA0 = s2u(scal0 + 1);
    } else if (tid == 253) {         // h1.h1 -> scal1[1]
        mode = 1;
        v0 = s2u(hs1);
        oA0 = s2u(scal1 + 1);
    }

    ull wA[50], wB[50];
    {
        const ull* a  = (const ull*)wpA;
        const ull* b2 = (const ull*)(wpA + 100);
        float2 cst = make_float2(wBconst, wBconst);
        ull cstu = *(ull*)&cst;
        #pragma unroll
        for (int i = 0; i < 50; i++) {
            wA[i] = a[i];
            wB[i] = fromMem ? b2[i] : cstu;
        }
    }

    // ---- per-thread state (tid 0-199: elementwise owner) ----
    const int batch = (tid >= 100);
    const int ei    = tid - 100 * batch;          // element index 0..99
    float hreg = 0.f, sreg = 0.f;
    if (tid < 100) { hs0[tid] = 0.f; hs1[tid] = 0.f; ss0[tid] = 0.f; ss1[tid] = 0.f; }

    float bti = 0.f, bts = 0.f;
    int   len = 0;
    const float* xpb = g_xp;
    float* hsP = hs0; float* ssP = ss0;
    const float* hpP = hp0; const float* tivP = tiv0; const float* tssP = tss0;
    const float* scalP = scal0;
    if (tid < 200) {
        bti = b_ti[ei]; bts = b_ts[ei];
        len = lens[b0 + batch];
        xpb = g_xp + (size_t)(b0 + batch) * T_ * G3_;
        if (batch) { hsP = hs1; ssP = ss1; hpP = hp1; tivP = tiv1; tssP = tss1; scalP = scal1; }
    }
    const float blgr = b_lgr[0];

    float xv0 = 0.f, xv1 = 0.f, xv2 = 0.f;
    float xn0 = 0.f, xn1 = 0.f, xn2 = 0.f;
    if (tid < 200) {
        xv0 = xpb[ei]; xv1 = xpb[100 + ei]; xv2 = xpb[200 + ei];
    }
    __syncthreads();

    for (int t = 0; t <= T_; ++t) {
        // ---------------- Stage 1 ----------------
        if (tid < 200 && t + 1 < T_) {
            const float* x = xpb + (size_t)(t + 1) * G3_;
            xn0 = x[ei]; xn1 = x[100 + ei]; xn2 = x[200 + ei];
        }

        const bool act = (mode == 0) ? (hhRow ? (t < T_) : (t >= 1))
                                     : (mode == 1 && t >= 1);
        if (mode == 0 && act) {
            ull a0 = 0ull, a1 = 0ull, bb0 = 0ull, bb1 = 0ull;
            ull c0 = 0ull, c1 = 0ull, d0 = 0ull, d1 = 0ull;
            #pragma unroll
            for (int i = 0; i < 25; i++) {
                ull hx0, hy0, hx1, hy1;
                asm volatile("ld.shared.v2.b64 {%0, %1}, [%2];"
                             : "=l"(hx0), "=l"(hy0) : "r"(v0 + i * 16));
                asm volatile("ld.shared.v2.b64 {%0, %1}, [%2];"
                             : "=l"(hx1), "=l"(hy1) : "r"(v1 + i * 16));
                FMA2(a0,  wA[2 * i],     hx0, a0);
                FMA2(a1,  wA[2 * i + 1], hy0, a1);
                FMA2(bb0, wB[2 * i],     hx0, bb0);
                FMA2(bb1, wB[2 * i + 1], hy0, bb1);
                FMA2(c0,  wA[2 * i],     hx1, c0);
                FMA2(c1,  wA[2 * i + 1], hy1, c1);
                FMA2(d0,  wB[2 * i],     hx1, d0);
                FMA2(d1,  wB[2 * i + 1], hy1, d1);
            }
            ull ta, tb, tc, td;
            ADD2(ta, a0, a1);
            ADD2(tb, bb0, bb1);
            ADD2(tc, c0, c1);
            ADD2(td, d0, d1);
            float rA0 = sum2(ta) + biasA;
            float rB0 = sum2(tb) + biasB;
            float rA1 = sum2(tc) + biasA;
            float rB1 = sum2(td) + biasB;
            asm volatile("st.shared.f32 [%0], %1;" :: "r"(oA0), "f"(rA0));
            asm volatile("st.shared.f32 [%0], %1;" :: "r"(oB0), "f"(rB0));
            asm volatile("st.shared.f32 [%0], %1;" :: "r"(oA1), "f"(rA1));
            asm volatile("st.shared.f32 [%0], %1;" :: "r"(oB1), "f"(rB1));
        } else if (mode == 1 && act) {
            ull a0 = 0ull, a1 = 0ull;
            #pragma unroll
            for (int i = 0; i < 25; i++) {
                ull hx, hy;
                asm volatile("ld.shared.v2.b64 {%0, %1}, [%2];"
                             : "=l"(hx), "=l"(hy) : "r"(v0 + i * 16));
                FMA2(a0, hx, hx, a0);
                FMA2(a1, hy, hy, a1);
            }
            ull ta;
            ADD2(ta, a0, a1);
            float rA = sum2(ta);
            asm volatile("st.shared.f32 [%0], %1;" :: "r"(oA0), "f"(rA));
        }
        __syncthreads();

        // ---------------- Stage 2 ----------------
        if (tid < 200) {
            if (t < T_) {
                float rr = sigmoidf_(xv0 + hpP[ei]);
                float z  = sigmoidf_(xv1 + hpP[100 + ei]);
                float ng = tanhf    (xv2 + rr * hpP[200 + ei]);
                hreg = (1.f - z) * ng + z * hreg;
                hsP[ei] = hreg;
                xv0 = xn0; xv1 = xn1; xv2 = xn2;
            }
            if (t >= 1) {
                float hsum = scalP[0], h2 = scalP[1], li = scalP[2], wd = scalP[3];
                float att  = 0.001f * hsum / fmaxf(sqrtf(h2), 1e-12f);
                float zt   = (t - 1 < len) ? fmaxf(att, 0.f) : 0.f;
                float gate = sigmoidf_(li + wd + blgr);
                float ns   = tanhf(tivP[ei] + bti + gate * tssP[ei] + bts);
                sreg = (1.f - zt) * sreg + zt * ns;
                ssP[ei] = sreg;
            }
        }
        __syncthreads();
    }

    // output head
    if (tid < NC_) {
        float a = b_out[tid];
        for (int k = 0; k < 100; ++k)
            a = fmaf(W_out[tid * 100 + k], ss0[k], a);
        out[b0 * NC_ + tid] = a;
    } else if (tid >= 32 && tid < 32 + NC_) {
        int c = tid - 32;
        float a = b_out[c];
        for (int k = 0; k < 100; ++k)
            a = fmaf(W_out[c * 100 + k], ss1[k], a);
        out[(b0 + 1) * NC_ + c] = a;
    }
}

extern "C" void kernel_launch(void* const* d_in, const int* in_sizes, int n_in,
                              void* d_out, int out_size)
{
    const int*   txt   = (const int*)  d_in[0];
    const int*   lens  = (const int*)  d_in[1];
    const float* emb   = (const float*)d_in[2];
    const float* W_ih  = (const float*)d_in[3];
    const float* W_hh  = (const float*)d_in[4];
    const float* b_ih  = (const float*)d_in[5];
    const float* b_hh  = (const float*)d_in[6];
    const float* W_lgr = (const float*)d_in[7];
    const float* b_lgr = (const float*)d_in[8];
    const float* W_ts  = (const float*)d_in[9];
    const float* b_ts  = (const float*)d_in[10];
    const float* W_ti  = (const float*)d_in[11];
    const float* b_ti  = (const float*)d_in[12];
    const float* W_out = (const float*)d_in[13];
    const float* b_out = (const float*)d_in[14];
    float* out = (float*)d_out;

    cudaFuncSetAttribute(xp_kernel,
                         cudaFuncAttributeMaxDynamicSharedMemorySize,
                         A_SMEM_BYTES);

    xp_kernel<<<(B_ * T_) / 32, 256, A_SMEM_BYTES>>>(txt, emb, W_ih, b_ih);
    scan_kernel<<<B_ / 2, 256>>>(lens,
                                 W_hh, b_hh, W_lgr, b_lgr,
                                 W_ts, b_ts, W_ti, b_ti,
                                 W_out, b_out, out);
}

// round 9
// speedup vs baseline: 1.9884x; 1.1576x over previous
#include <cuda_runtime.h>
#include <cstdint>
#include <cstddef>

#define B_  256
#define T_  512
#define E_  200
#define H_  100
#define G3_ 300
#define NC_ 5

typedef unsigned long long ull;

// 256*512*300 floats = 157 MB scratch for GRU input preactivations.
__device__ float g_xp[39321600];

// packed fp32x2 FMA / ADD (Blackwell sm_103a); exact per-lane fp32 semantics
#define FMA2(d, a, b, c) \
    asm("fma.rn.f32x2 %0, %1, %2, %3;" : "=l"(d) : "l"(a), "l"(b), "l"(c))
#define ADD2(d, a, b) \
    asm("add.rn.f32x2 %0, %1, %2;" : "=l"(d) : "l"(a), "l"(b))
#define DUP2(d, a) \
    asm("mov.b64 %0, {%1, %1};" : "=l"(d) : "f"(a))

__device__ __forceinline__ float sigmoidf_(float x) {
    return 1.0f / (1.0f + __expf(-x));
}

__device__ __forceinline__ float sum2(ull v) {
    float a, b_;
    asm("mov.b64 {%0, %1}, %2;" : "=f"(a), "=f"(b_) : "l"(v));
    return a + b_;
}

__device__ __forceinline__ uint32_t s2u(const void* p) {
    return (uint32_t)__cvta_generic_to_shared(p);
}

// ---------------------------------------------------------------------------
// Kernel A: xp[row,:] = scale(row) * (emb[txt[row]] @ W_ih^T) + b_ih
// 64 rows x 300 cols per block. Per-thread 8x10 tile (40 f32x2 accumulators).
// e tile scalar in SMEM (lane-dup via mov.b64 on alu pipe); W chunk staged
// [kk][300]: &wst[kk*300 + cg*10] is 8B-aligned (40*cg) and LDS.64
// conflict-free (cg*10 mod 32 distinct within each 16-lane phase).
// ---------------------------------------------------------------------------
#define AR_ 64
#define A_ES_OFF    0                         // float[64*200] = 51200 B
#define A_WST_OFF   51200                     // float[10*300] = 12000 B
#define A_SC_OFF    (A_WST_OFF + 12000)       // float[64]
#define A_N2_OFF    (A_SC_OFF + 256)          // float[64]
#define A_TOK_OFF   (A_N2_OFF + 256)          // int[64]
#define A_SMEM_BYTES (A_TOK_OFF + 256)

__global__ void __launch_bounds__(256) xp_kernel(
    const int* __restrict__ txt, const float* __restrict__ emb,
    const float* __restrict__ W_ih, const float* __restrict__ b_ih)
{
    extern __shared__ char asm_[];
    float* es  = (float*)(asm_ + A_ES_OFF);     // [64][200]
    float* wst = (float*)(asm_ + A_WST_OFF);    // [10][300]
    float* sc  = (float*)(asm_ + A_SC_OFF);
    float* n2  = (float*)(asm_ + A_N2_OFF);
    int*   toks= (int*)  (asm_ + A_TOK_OFF);

    const int tid  = threadIdx.x;
    const int row0 = blockIdx.x * AR_;

    if (tid < AR_) { toks[tid] = txt[row0 + tid]; n2[tid] = 0.f; }
    __syncthreads();

    // gather raw embedding rows (scalar)
    for (int idx = tid; idx < AR_ * 200; idx += 256) {
        int r = idx / 200, k = idx - r * 200;
        es[r * 200 + k] = emb[(size_t)toks[r] * E_ + k];
    }
    __syncthreads();

    // row norms: 2 threads per row
    if (tid < 128) {
        int r = tid >> 1, q = tid & 1;
        float p = 0.f;
        for (int k = q * 100; k < q * 100 + 100; ++k) {
            float v = es[r * 200 + k];
            p = fmaf(v, v, p);
        }
        atomicAdd(&n2[r], p);
    }
    __syncthreads();
    if (tid < AR_) {
        float n = sqrtf(n2[tid]);
        sc[tid] = (n > 1.0f) ? 1.0f / (n + 1e-7f) : 1.0f;
    }
    __syncthreads();

    const int cg = tid % 30;   // cols cg*10 .. cg*10+9
    const int rg = tid / 30;   // rows rg*8 .. rg*8+7 (active if tid<240)

    ull acc[8][5];
    #pragma unroll
    for (int i = 0; i < 8; i++)
        #pragma unroll
        for (int j = 0; j < 5; j++) acc[i][j] = 0ull;

    for (int k0 = 0; k0 < 200; k0 += 10) {
        // stage W chunk transposed: wst[kk][c] = W_ih[c][k0+kk]
        for (int idx = tid; idx < 3000; idx += 256) {
            int c = idx / 10, kk = idx - c * 10;
            wst[kk * 300 + c] = W_ih[c * 200 + k0 + kk];
        }
        __syncthreads();
        if (tid < 240) {
            #pragma unroll
            for (int kk = 0; kk < 10; kk++) {
                ull e2[8];
                #pragma unroll
                for (int i = 0; i < 8; i++) {
                    float ev = es[(rg * 8 + i) * 200 + k0 + kk];
                    DUP2(e2[i], ev);
                }
                const ull* wr = (const ull*)&wst[kk * 300 + cg * 10];
                #pragma unroll
                for (int j = 0; j < 5; j++) {
                    ull w = wr[j];
                    #pragma unroll
                    for (int i = 0; i < 8; i++)
                        FMA2(acc[i][j], e2[i], w, acc[i][j]);
                }
            }
        }
        __syncthreads();
    }

    if (tid < 240) {
        float2 bih[5];
        const float2* bih2 = (const float2*)b_ih;   // cg*10 even -> aligned
        #pragma unroll
        for (int j = 0; j < 5; j++) bih[j] = bih2[cg * 5 + j];
        #pragma unroll
        for (int i = 0; i < 8; i++) {
            int r = rg * 8 + i;
            float s = sc[r];
            float2* outp = (float2*)(g_xp + (size_t)(row0 + r) * G3_ + cg * 10);
            #pragma unroll
            for (int j = 0; j < 5; j++) {
                float2 a = *(float2*)&acc[i][j];
                float2 v;
                v.x = fmaf(s, a.x, bih[j].x);
                v.y = fmaf(s, a.y, bih[j].y);
                outp[j] = v;
            }
        }
    }
}

// ---------------------------------------------------------------------------
// Kernel B: fused scan, two batch elements per CTA sharing register-resident
// weights (unchanged — near its fp32 pipe roofline).
// ---------------------------------------------------------------------------
__global__ void __launch_bounds__(256, 1) scan_kernel(
    const int*   __restrict__ lens,
    const float* __restrict__ W_hh, const float* __restrict__ b_hh,
    const float* __restrict__ W_lgr, const float* __restrict__ b_lgr,
    const float* __restrict__ W_ts, const float* __restrict__ b_ts,
    const float* __restrict__ W_ti, const float* __restrict__ b_ti,
    const float* __restrict__ W_out, const float* __restrict__ b_out,
    float* __restrict__ out)
{
    __shared__ __align__(16) float hs0[100], hs1[100];
    __shared__ __align__(16) float ss0[100], ss1[100];
    __shared__ __align__(16) float hp0[300], hp1[300];
    __shared__ __align__(16) float tiv0[100], tiv1[100];
    __shared__ __align__(16) float tss0[100], tss1[100];
    __shared__ __align__(16) float scal0[4], scal1[4];
    __shared__ __align__(16) float dummy[8];

    const int tid = threadIdx.x;
    const int b0  = blockIdx.x * 2;

    int   mode  = 2;                 // 0: dot, 1: sumsq, 2: idle
    int   hhRow = 0;
    const float* wpA = W_hh;
    int   fromMem = 1;
    float wBconst = 0.f;
    float biasA = 0.f, biasB = 0.f;
    uint32_t v0  = s2u(hs0), v1  = s2u(hs1);
    uint32_t oA0 = s2u(dummy), oB0 = s2u(dummy + 1);
    uint32_t oA1 = s2u(dummy + 2), oB1 = s2u(dummy + 3);

    const int r = 2 * tid;
    if (tid < 150) {
        mode = 0; hhRow = 1;
        wpA = W_hh + (size_t)r * 100;
        biasA = b_hh[r]; biasB = b_hh[r + 1];
        v0 = s2u(hs0); v1 = s2u(hs1);
        oA0 = s2u(hp0 + r); oB0 = s2u(hp0 + r + 1);
        oA1 = s2u(hp1 + r); oB1 = s2u(hp1 + r + 1);
    } else if (tid < 200) {
        mode = 0;
        wpA = W_ti + (size_t)(r - 300) * 100;
        v0 = s2u(hs0); v1 = s2u(hs1);
        oA0 = s2u(tiv0 + (r - 300)); oB0 = s2u(tiv0 + (r - 299));
        oA1 = s2u(tiv1 + (r - 300)); oB1 = s2u(tiv1 + (r - 299));
    } else if (tid < 250) {
        mode = 0;
        wpA = W_ts + (size_t)(r - 400) * 100;
        v0 = s2u(ss0); v1 = s2u(ss1);
        oA0 = s2u(tss0 + (r - 400)); oB0 = s2u(tss0 + (r - 399));
        oA1 = s2u(tss1 + (r - 400)); oB1 = s2u(tss1 + (r - 399));
    } else if (tid == 250) {
        mode = 0;
        wpA = W_lgr;
        fromMem = 0; wBconst = 1.0f;
        v0 = s2u(hs0); v1 = s2u(hs1);
        oA0 = s2u(scal0 + 2); oB0 = s2u(scal0 + 0);
        oA1 = s2u(scal1 + 2); oB1 = s2u(scal1 + 0);
    } else if (tid == 251) {
        mode = 0;
        wpA = W_lgr + 100;
        fromMem = 0; wBconst = 0.0f;
        v0 = s2u(ss0); v1 = s2u(ss1);
        oA0 = s2u(scal0 + 3); oB0 = s2u(dummy + 4);
        oA1 = s2u(scal1 + 3); oB1 = s2u(dummy + 5);
    } else if (tid == 252) {
        mode = 1;
        v0 = s2u(hs0);
        oA0 = s2u(scal0 + 1);
    } else if (tid == 253) {
        mode = 1;
        v0 = s2u(hs1);
        oA0 = s2u(scal1 + 1);
    }

    ull wA[50], wB[50];
    {
        const ull* a  = (const ull*)wpA;
        const ull* b2 = (const ull*)(wpA + 100);
        float2 cst = make_float2(wBconst, wBconst);
        ull cstu = *(ull*)&cst;
        #pragma unroll
        for (int i = 0; i < 50; i++) {
            wA[i] = a[i];
            wB[i] = fromMem ? b2[i] : cstu;
        }
    }

    const int batch = (tid >= 100);
    const int ei    = tid - 100 * batch;
    float hreg = 0.f, sreg = 0.f;
    if (tid < 100) { hs0[tid] = 0.f; hs1[tid] = 0.f; ss0[tid] = 0.f; ss1[tid] = 0.f; }

    float bti = 0.f, bts = 0.f;
    int   len = 0;
    const float* xpb = g_xp;
    float* hsP = hs0; float* ssP = ss0;
    const float* hpP = hp0; const float* tivP = tiv0; const float* tssP = tss0;
    const float* scalP = scal0;
    if (tid < 200) {
        bti = b_ti[ei]; bts = b_ts[ei];
        len = lens[b0 + batch];
        xpb = g_xp + (size_t)(b0 + batch) * T_ * G3_;
        if (batch) { hsP = hs1; ssP = ss1; hpP = hp1; tivP = tiv1; tssP = tss1; scalP = scal1; }
    }
    const float blgr = b_lgr[0];

    float xv0 = 0.f, xv1 = 0.f, xv2 = 0.f;
    float xn0 = 0.f, xn1 = 0.f, xn2 = 0.f;
    if (tid < 200) {
        xv0 = xpb[ei]; xv1 = xpb[100 + ei]; xv2 = xpb[200 + ei];
    }
    __syncthreads();

    for (int t = 0; t <= T_; ++t) {
        // ---------------- Stage 1 ----------------
        if (tid < 200 && t + 1 < T_) {
            const float* x = xpb + (size_t)(t + 1) * G3_;
            xn0 = x[ei]; xn1 = x[100 + ei]; xn2 = x[200 + ei];
        }

        const bool act = (mode == 0) ? (hhRow ? (t < T_) : (t >= 1))
                                     : (mode == 1 && t >= 1);
        if (mode == 0 && act) {
            ull a0 = 0ull, a1 = 0ull, bb0 = 0ull, bb1 = 0ull;
            ull c0 = 0ull, c1 = 0ull, d0 = 0ull, d1 = 0ull;
            #pragma unroll
            for (int i = 0; i < 25; i++) {
                ull hx0, hy0, hx1, hy1;
                asm volatile("ld.shared.v2.b64 {%0, %1}, [%2];"
                             : "=l"(hx0), "=l"(hy0) : "r"(v0 + i * 16));
                asm volatile("ld.shared.v2.b64 {%0, %1}, [%2];"
                             : "=l"(hx1), "=l"(hy1) : "r"(v1 + i * 16));
                FMA2(a0,  wA[2 * i],     hx0, a0);
                FMA2(a1,  wA[2 * i + 1], hy0, a1);
                FMA2(bb0, wB[2 * i],     hx0, bb0);
                FMA2(bb1, wB[2 * i + 1], hy0, bb1);
                FMA2(c0,  wA[2 * i],     hx1, c0);
                FMA2(c1,  wA[2 * i + 1], hy1, c1);
                FMA2(d0,  wB[2 * i],     hx1, d0);
                FMA2(d1,  wB[2 * i + 1], hy1, d1);
            }
            ull ta, tb, tc, td;
            ADD2(ta, a0, a1);
            ADD2(tb, bb0, bb1);
            ADD2(tc, c0, c1);
            ADD2(td, d0, d1);
            float rA0 = sum2(ta) + biasA;
            float rB0 = sum2(tb) + biasB;
            float rA1 = sum2(tc) + biasA;
            float rB1 = sum2(td) + biasB;
            asm volatile("st.shared.f32 [%0], %1;" :: "r"(oA0), "f"(rA0));
            asm volatile("st.shared.f32 [%0], %1;" :: "r"(oB0), "f"(rB0));
            asm volatile("st.shared.f32 [%0], %1;" :: "r"(oA1), "f"(rA1));
            asm volatile("st.shared.f32 [%0], %1;" :: "r"(oB1), "f"(rB1));
        } else if (mode == 1 && act) {
            ull a0 = 0ull, a1 = 0ull;
            #pragma unroll
            for (int i = 0; i < 25; i++) {
                ull hx, hy;
                asm volatile("ld.shared.v2.b64 {%0, %1}, [%2];"
                             : "=l"(hx), "=l"(hy) : "r"(v0 + i * 16));
                FMA2(a0, hx, hx, a0);
                FMA2(a1, hy, hy, a1);
            }
            ull ta;
            ADD2(ta, a0, a1);
            float rA = sum2(ta);
            asm volatile("st.shared.f32 [%0], %1;" :: "r"(oA0), "f"(rA));
        }
        __syncthreads();

        // ---------------- Stage 2 ----------------
        if (tid < 200) {
            if (t < T_) {
                float rr = sigmoidf_(xv0 + hpP[ei]);
                float z  = sigmoidf_(xv1 + hpP[100 + ei]);
                float ng = tanhf    (xv2 + rr * hpP[200 + ei]);
                hreg = (1.f - z) * ng + z * hreg;
                hsP[ei] = hreg;
                xv0 = xn0; xv1 = xn1; xv2 = xn2;
            }
            if (t >= 1) {
                float hsum = scalP[0], h2 = scalP[1], li = scalP[2], wd = scalP[3];
                float att  = 0.001f * hsum / fmaxf(sqrtf(h2), 1e-12f);
                float zt   = (t - 1 < len) ? fmaxf(att, 0.f) : 0.f;
                float gate = sigmoidf_(li + wd + blgr);
                float ns   = tanhf(tivP[ei] + bti + gate * tssP[ei] + bts);
                sreg = (1.f - zt) * sreg + zt * ns;
                ssP[ei] = sreg;
            }
        }
        __syncthreads();
    }

    if (tid < NC_) {
        float a = b_out[tid];
        for (int k = 0; k < 100; ++k)
            a = fmaf(W_out[tid * 100 + k], ss0[k], a);
        out[b0 * NC_ + tid] = a;
    } else if (tid >= 32 && tid < 32 + NC_) {
        int c = tid - 32;
        float a = b_out[c];
        for (int k = 0; k < 100; ++k)
            a = fmaf(W_out[c * 100 + k], ss1[k], a);
        out[(b0 + 1) * NC_ + c] = a;
    }
}

extern "C" void kernel_launch(void* const* d_in, const int* in_sizes, int n_in,
                              void* d_out, int out_size)
{
    const int*   txt   = (const int*)  d_in[0];
    const int*   lens  = (const int*)  d_in[1];
    const float* emb   = (const float*)d_in[2];
    const float* W_ih  = (const float*)d_in[3];
    const float* W_hh  = (const float*)d_in[4];
    const float* b_ih  = (const float*)d_in[5];
    const float* b_hh  = (const float*)d_in[6];
    const float* W_lgr = (const float*)d_in[7];
    const float* b_lgr = (const float*)d_in[8];
    const float* W_ts  = (const float*)d_in[9];
    const float* b_ts  = (const float*)d_in[10];
    const float* W_ti  = (const float*)d_in[11];
    const float* b_ti  = (const float*)d_in[12];
    const float* W_out = (const float*)d_in[13];
    const float* b_out = (const float*)d_in[14];
    float* out = (float*)d_out;

    cudaFuncSetAttribute(xp_kernel,
                         cudaFuncAttributeMaxDynamicSharedMemorySize,
                         A_SMEM_BYTES);

    xp_kernel<<<(B_ * T_) / AR_, 256, A_SMEM_BYTES>>>(txt, emb, W_ih, b_ih);
    scan_kernel<<<B_ / 2, 256>>>(lens,
                                 W_hh, b_hh, W_lgr, b_lgr,
                                 W_ts, b_ts, W_ti, b_ti,
                                 W_out, b_out, out);
}